// round 15
// baseline (speedup 1.0000x reference)
#include <cuda_runtime.h>
#include <cuda_bf16.h>

#define BB 128
#define NN 512
#define CF 64
#define LOG2E 1.4426950408889634f

typedef unsigned int u32;
typedef unsigned long long u64;

// ---------------- scratch ----------------
__device__ u32 g_adjb[NN * 16];

// ---------------- helpers ----------------
__device__ __forceinline__ u32 cvt2(float vh, float vl) {     // bf16x2 pack
    u32 r; asm("cvt.rn.bf16x2.f32 %0, %1, %2;" : "=r"(r) : "f"(vh), "f"(vl));
    return r;
}
__device__ __forceinline__ u32 cvth2(float vh, float vl) {    // f16x2 pack
    u32 r; asm("cvt.rn.f16x2.f32 %0, %1, %2;" : "=r"(r) : "f"(vh), "f"(vl));
    return r;
}
__device__ __forceinline__ float2 h2f2(u32 p) {               // unpack f16x2 -> 2 f32
    float2 r;
    asm("{.reg .f16 lo, hi;\n\t mov.b32 {lo, hi}, %2;\n\t"
        "cvt.f32.f16 %0, lo;\n\t cvt.f32.f16 %1, hi;}"
        : "=f"(r.x), "=f"(r.y) : "r"(p));
    return r;
}
__device__ __forceinline__ u32 ex2h2(u32 x) {                 // packed fp16 2^x
    u32 r; asm("ex2.approx.f16x2 %0, %1;" : "=r"(r) : "r"(x));
    return r;
}
__device__ __forceinline__ float bflo_f(u32 p) { return __uint_as_float(p << 16); }
__device__ __forceinline__ float bfhi_f(u32 p) { return __uint_as_float(p & 0xFFFF0000u); }
__device__ __forceinline__ u32 smem_u32(const void* p) {
    u32 a;
    asm("{ .reg .u64 t; cvta.to.shared.u64 t, %1; cvt.u32.u64 %0, t; }"
        : "=r"(a) : "l"(p));
    return a;
}
// w = bit ? exp2(lrelu(v) - M) : 0   (v pre-scaled by log2 e; M = row bound)
__device__ __forceinline__ float wcalc(float v, u32 bit, float M) {
    float u = fmaxf(v, 0.2f * v) - M;
    u = bit ? u : -1e38f;
    float e; asm("ex2.approx.f32 %0, %1;" : "=f"(e) : "f"(u));
    return e;
}

#define LDSM4(r0, r1, r2, r3, addr) \
    asm volatile("ldmatrix.sync.aligned.m8n8.x4.shared.b16 {%0,%1,%2,%3}, [%4];" \
        : "=r"(r0), "=r"(r1), "=r"(r2), "=r"(r3) : "r"(addr))

#define LDSM4T(r0, r1, r2, r3, addr) \
    asm volatile("ldmatrix.sync.aligned.m8n8.x4.trans.shared.b16 {%0,%1,%2,%3}, [%4];" \
        : "=r"(r0), "=r"(r1), "=r"(r2), "=r"(r3) : "r"(addr))

#define MMA_F16(d, a0, a1, a2, a3, b0, b1) \
    asm volatile("mma.sync.aligned.m16n8k16.row.col.f32.f16.f16.f32 " \
        "{%0,%1,%2,%3}, {%4,%5,%6,%7}, {%8,%9}, {%0,%1,%2,%3};" \
        : "+f"((d)[0]), "+f"((d)[1]), "+f"((d)[2]), "+f"((d)[3]) \
        : "r"(a0), "r"(a1), "r"(a2), "r"(a3), "r"(b0), "r"(b1))

// swizzled byte offset within 128B-row layout: row j, 4-byte pair index f2 (0..31)
__device__ __forceinline__ u32 swoff(int j, int f2) {
    return (u32)(j * 128 + ((((f2 >> 2) ^ (j & 7))) << 4) + ((f2 & 3) << 2));
}

// ---------------------------------------------------------------------------
// Kernel 1: adj -> bitmask
// ---------------------------------------------------------------------------
__global__ __launch_bounds__(512) void adj_bits_kernel(const int* __restrict__ adj) {
    int row = blockIdx.x;
    int t = threadIdx.x;
    int v = adj[(size_t)row * NN + t];
    u32 m = __ballot_sync(0xffffffffu, v > 0);
    if ((t & 31) == 0) g_adjb[row * 16 + (t >> 5)] = m;
}

// ---------------------------------------------------------------------------
// Kernel 2: fused GEMM + attention. 1 CTA/batch, 512 threads (16 warps).
// Phase 1: hS = x@(W0+W1) fp16 3-pass, h1 = x@W1 fp16 1-pass; diff = hS-2*h1.
// Phase 2: 1-pass fp16 HMMA attention, software-pipelined weight generation.
// ---------------------------------------------------------------------------
#define SM_H    0                 // x hi/lo (phase1) ; h1 fp16 in first 64KB (phase2)
#define SM_W    131072            // WS_hi, WS_lo, W1 : 3 x 8192
#define SM_ADJ  163840            // chunk-major: [chunk][row] 16x512 u32
#define SM_Z    196608            // 1024 f32: interleaved (p, 0.2p) per j
#define SM_AS   200704            // a vector: 128 f32
#define SM_BIAS 201216            // 64 f32
#define SM_WMAX 201472            // 16 f32
#define SMEM_SZ 201536

__global__ __launch_bounds__(512) void gat_fused_kernel(
    const float* __restrict__ x, const float* __restrict__ W,
    const float* __restrict__ a, const float* __restrict__ bias,
    float* __restrict__ out)
{
    extern __shared__ char smc[];
    int b = blockIdx.x;
    int t = threadIdx.x;
    u32 smb = smem_u32(smc);

    float* zs  = (float*)(smc + SM_Z);
    float* asv = (float*)(smc + SM_AS);
    float* bs  = (float*)(smc + SM_BIAS);
    float* wmx = (float*)(smc + SM_WMAX);
    u32*  adjs = (u32*)(smc + SM_ADJ);

    // ---- stage: x (fp32 -> fp16 hi/lo, swizzled rows), WS/W1, adj, a, bias --
    {
        const float4* xp = (const float4*)(x + (size_t)b * NN * CF);
        #pragma unroll
        for (int k = 0; k < 16; k++) {
            int idx = t + k * 512;
            float4 v = __ldg(xp + idx);
            int row = idx >> 4;
            int f2  = (idx & 15) << 1;
            u32 h0 = cvth2(v.y, v.x);
            float2 f0 = h2f2(h0);
            u32 l0 = cvth2(v.y - f0.y, v.x - f0.x);
            u32 h1 = cvth2(v.w, v.z);
            float2 f1 = h2f2(h1);
            u32 l1 = cvth2(v.w - f1.y, v.z - f1.x);
            u32 o0 = swoff(row, f2), o1 = swoff(row, f2 + 1);
            *(u32*)(smc + SM_H + o0) = h0;
            *(u32*)(smc + SM_H + 65536 + o0) = l0;
            *(u32*)(smc + SM_H + o1) = h1;
            *(u32*)(smc + SM_H + 65536 + o1) = l1;
        }
        const float4* wp = (const float4*)W;
        #pragma unroll
        for (int k = 0; k < 2; k++) {
            int idx = t + k * 512;
            float4 v0 = __ldg(wp + idx);
            float4 v1 = __ldg(wp + 1024 + idx);
            int c = idx >> 4;
            int f2 = (idx & 15) << 1;
            float sx = v0.x + v1.x, sy = v0.y + v1.y;
            float sz = v0.z + v1.z, sw = v0.w + v1.w;
            u32 hs0 = cvth2(sy, sx);
            float2 fs0 = h2f2(hs0);
            u32 ls0 = cvth2(sy - fs0.y, sx - fs0.x);
            u32 hs1 = cvth2(sw, sz);
            float2 fs1 = h2f2(hs1);
            u32 ls1 = cvth2(sw - fs1.y, sz - fs1.x);
            u32 o0 = swoff(c, f2), o1 = swoff(c, f2 + 1);
            *(u32*)(smc + SM_W + o0) = hs0;
            *(u32*)(smc + SM_W + 8192 + o0) = ls0;
            *(u32*)(smc + SM_W + o1) = hs1;
            *(u32*)(smc + SM_W + 8192 + o1) = ls1;
            *(u32*)(smc + SM_W + 16384 + o0) = cvth2(v1.y, v1.x);
            *(u32*)(smc + SM_W + 16384 + o1) = cvth2(v1.w, v1.z);
        }
        #pragma unroll
        for (int k = 0; k < 16; k++)
            adjs[(k << 9) + t] = g_adjb[t * 16 + k];
        if (t < 128) asv[t] = __ldg(&a[t]);
        if (t < 64) bs[t] = __ldg(&bias[t]);
    }
    __syncthreads();

    int lane = t & 31, w = t >> 5;
    int qid = lane & 3, gid = lane >> 2;
    int klane = lane & 15;
    int nhalf = lane >> 4;
    int k7 = klane & 7;
    int cHalf = lane >> 4;

    u32 cswz[4];
    #pragma unroll
    for (int g = 0; g < 4; g++)
        cswz[g] = (u32)(((((g << 1) + nhalf)) ^ k7) << 4);

    // ---------------- phase 1: hS (3-pass) + h1 (1-pass) fp16 HMMA ---------
    u32 diffA[2][8], diffB[2][8];
    float s1reg[2], s1reg2[2];

    #pragma unroll
    for (int rt = 0; rt < 2; rt++) {
        int rbg = w * 32 + rt * 16;
        int rowA = rbg + (lane & 15);
        u32 aBase = smb + SM_H + rowA * 128;
        int r7x = rowA & 7;

        float d0[8][4], d1[8][4];
        #pragma unroll
        for (int i = 0; i < 8; i++)
            #pragma unroll
            for (int e = 0; e < 4; e++) { d0[i][e] = 0.f; d1[i][e] = 0.f; }

        #pragma unroll
        for (int ks = 0; ks < 4; ks++) {
            u32 achunk = (u32)(((2 * ks + cHalf) ^ r7x) << 4);
            u32 ah0, ah1, ah2, ah3, al0, al1, al2, al3;
            LDSM4(ah0, ah1, ah2, ah3, aBase + achunk);
            LDSM4(al0, al1, al2, al3, aBase + 65536 + achunk);
            u32 kb = (u32)((ks * 16 + klane) * 128);
            #pragma unroll
            for (int g = 0; g < 4; g++) {
                u32 cs = cswz[g];
                u32 b0, b1, b2, b3;
                LDSM4T(b0, b1, b2, b3, smb + SM_W + cs + kb);           // WS hi
                MMA_F16(d0[2 * g],     ah0, ah1, ah2, ah3, b0, b1);
                MMA_F16(d0[2 * g + 1], ah0, ah1, ah2, ah3, b2, b3);
                MMA_F16(d0[2 * g],     al0, al1, al2, al3, b0, b1);
                MMA_F16(d0[2 * g + 1], al0, al1, al2, al3, b2, b3);
                LDSM4T(b0, b1, b2, b3, smb + SM_W + 8192 + cs + kb);    // WS lo
                MMA_F16(d0[2 * g],     ah0, ah1, ah2, ah3, b0, b1);
                MMA_F16(d0[2 * g + 1], ah0, ah1, ah2, ah3, b2, b3);
                LDSM4T(b0, b1, b2, b3, smb + SM_W + 16384 + cs + kb);   // W1
                MMA_F16(d1[2 * g],     ah0, ah1, ah2, ah3, b0, b1);
                MMA_F16(d1[2 * g + 1], ah0, ah1, ah2, ah3, b2, b3);
            }
        }

        // epilogue: s1/s2 from hS, diff = hS - 2*h1 (regs), h1 fp16 -> smem
        int r = rbg + gid, r2 = r + 8;
        float s1pA = 0.f, s2pA = 0.f, s1pB = 0.f, s2pB = 0.f;
        #pragma unroll
        for (int tI = 0; tI < 8; tI++) {
            int nc = tI * 8 + (qid << 1);
            float2 a1v = *(const float2*)(asv + nc);
            float2 a2v = *(const float2*)(asv + 64 + nc);
            int f2 = nc >> 1;
            {
                float hSa = d0[tI][0], hSb = d0[tI][1];
                float h1a = d1[tI][0], h1b = d1[tI][1];
                s1pA += hSa * a1v.x + hSb * a1v.y;
                s2pA += hSa * a2v.x + hSb * a2v.y;
                diffA[rt][tI] = cvt2(hSb - 2.f * h1b, hSa - 2.f * h1a);
                *(u32*)(smc + SM_H + swoff(r, f2)) = cvth2(h1b, h1a);
            }
            {
                float hSa = d0[tI][2], hSb = d0[tI][3];
                float h1a = d1[tI][2], h1b = d1[tI][3];
                s1pB += hSa * a1v.x + hSb * a1v.y;
                s2pB += hSa * a2v.x + hSb * a2v.y;
                diffB[rt][tI] = cvt2(hSb - 2.f * h1b, hSa - 2.f * h1a);
                *(u32*)(smc + SM_H + swoff(r2, f2)) = cvth2(h1b, h1a);
            }
        }
        s1pA += __shfl_xor_sync(0xffffffffu, s1pA, 1);
        s1pA += __shfl_xor_sync(0xffffffffu, s1pA, 2);
        s2pA += __shfl_xor_sync(0xffffffffu, s2pA, 1);
        s2pA += __shfl_xor_sync(0xffffffffu, s2pA, 2);
        s1pB += __shfl_xor_sync(0xffffffffu, s1pB, 1);
        s1pB += __shfl_xor_sync(0xffffffffu, s1pB, 2);
        s2pB += __shfl_xor_sync(0xffffffffu, s2pB, 1);
        s2pB += __shfl_xor_sync(0xffffffffu, s2pB, 2);
        s1reg[rt]  = s1pA * LOG2E;
        s1reg2[rt] = s1pB * LOG2E;
        if (qid == 0) {
            float p1 = s2pA * LOG2E, p2 = s2pB * LOG2E;
            zs[(r << 1)]      = p1;
            zs[(r << 1) + 1]  = 0.2f * p1;
            zs[(r2 << 1)]     = p2;
            zs[(r2 << 1) + 1] = 0.2f * p2;
        }
    }
    __syncthreads();   // h1 fp16 B-tiles + z table visible to all warps

    // ---- global max of s2 (for fp16-safe weight scaling) ----
    {
        float m = zs[(t & 511) << 1];
        #pragma unroll
        for (int o = 16; o; o >>= 1)
            m = fmaxf(m, __shfl_xor_sync(0xffffffffu, m, o));
        if (lane == 0) wmx[w] = m;
    }
    __syncthreads();
    float maxS2 = wmx[0];
    #pragma unroll
    for (int k = 1; k < 16; k++) maxS2 = fmaxf(maxS2, wmx[k]);

    // ---------------- phase 2: 1-pass fp16 HMMA attention (pipelined) ------
    u32 hbc[4];
    #pragma unroll
    for (int g = 0; g < 4; g++)
        hbc[g] = smb + SM_H + cswz[g];

    const u32 ONES = 0x3C003C00u;   // fp16 (1.0, 1.0)

    #pragma unroll
    for (int ph = 0; ph < 2; ph++) {
        int rbase = w * 32 + ph * 16;
        int r = rbase + gid, r2 = r + 8;
        float s1r = s1reg[ph], s1r2 = s1reg2[ph];
        float vm1 = s1r + maxS2, vm2 = s1r2 + maxS2;
        float M1 = fmaxf(vm1, 0.2f * vm1);
        float M2 = fmaxf(vm2, 0.2f * vm2);
        float A1 = s1r - M1,  B1 = 0.2f * s1r - M1;
        float A2 = s1r2 - M2, B2 = 0.2f * s1r2 - M2;

        float d[8][4];
        #pragma unroll
        for (int i = 0; i < 8; i++)
            #pragma unroll
            for (int k = 0; k < 4; k++) d[i][k] = 0.f;
        float dS[4] = {0.f, 0.f, 0.f, 0.f};

        // weight-gen for chunk cc -> packed fp16 fragments o0..o3
        #define WGEN(cc, o0, o1, o2, o3) do {                                  \
            int j0_ = (cc) << 4;                                               \
            float4 z0 = *(const float4*)(zs + ((j0_ + (qid << 1)) << 1));      \
            float4 z1 = *(const float4*)(zs + ((j0_ + 8 + (qid << 1)) << 1));  \
            u32 wr_  = adjs[(((cc) >> 1) << 9) + r];                           \
            u32 wr2_ = adjs[(((cc) >> 1) << 9) + r2];                          \
            int sh_ = (((cc) & 1) << 4) + (qid << 1);                          \
            u32 br_ = wr_ >> sh_, br2_ = wr2_ >> sh_;                          \
            float u00 = fmaxf(A1 + z0.x, B1 + z0.y);                           \
            float u01 = fmaxf(A1 + z0.z, B1 + z0.w);                           \
            float u08 = fmaxf(A1 + z1.x, B1 + z1.y);                           \
            float u09 = fmaxf(A1 + z1.z, B1 + z1.w);                           \
            float u10 = fmaxf(A2 + z0.x, B2 + z0.y);                           \
            float u11 = fmaxf(A2 + z0.z, B2 + z0.w);                           \
            float u18 = fmaxf(A2 + z1.x, B2 + z1.y);                           \
            float u19 = fmaxf(A2 + z1.z, B2 + z1.w);                           \
            u00 = (br_ & 1u)    ? u00 : -1e4f;                                 \
            u01 = (br_ & 2u)    ? u01 : -1e4f;                                 \
            u08 = (br_ & 256u)  ? u08 : -1e4f;                                 \
            u09 = (br_ & 512u)  ? u09 : -1e4f;                                 \
            u10 = (br2_ & 1u)   ? u10 : -1e4f;                                 \
            u11 = (br2_ & 2u)   ? u11 : -1e4f;                                 \
            u18 = (br2_ & 256u) ? u18 : -1e4f;                                 \
            u19 = (br2_ & 512u) ? u19 : -1e4f;                                 \
            o0 = ex2h2(cvth2(u01, u00));                                       \
            o1 = ex2h2(cvth2(u11, u10));                                       \
            o2 = ex2h2(cvth2(u09, u08));                                       \
            o3 = ex2h2(cvth2(u19, u18));                                       \
        } while (0)

        u32 a0, a1, a2, a3;
        WGEN(0, a0, a1, a2, a3);

        #pragma unroll 4
        for (int c = 0; c < 32; c++) {
            // B fragments for chunk c (issue early; consumed after WGEN)
            u32 kb = (u32)(((c << 4) + klane) << 7);
            u32 b00, b01, b02, b03, b10, b11, b12, b13;
            u32 b20, b21, b22, b23, b30, b31, b32, b33;
            LDSM4T(b00, b01, b02, b03, hbc[0] + kb);
            LDSM4T(b10, b11, b12, b13, hbc[1] + kb);
            LDSM4T(b20, b21, b22, b23, hbc[2] + kb);
            LDSM4T(b30, b31, b32, b33, hbc[3] + kb);

            MMA_F16(dS, a0, a1, a2, a3, ONES, ONES);   // row sums (a ready)

            // generate next chunk's fragments (overlaps MMA issue below)
            u32 n0, n1, n2, n3;
            int cn = (c + 1) & 31;
            WGEN(cn, n0, n1, n2, n3);

            MMA_F16(d[0], a0, a1, a2, a3, b00, b01);
            MMA_F16(d[1], a0, a1, a2, a3, b02, b03);
            MMA_F16(d[2], a0, a1, a2, a3, b10, b11);
            MMA_F16(d[3], a0, a1, a2, a3, b12, b13);
            MMA_F16(d[4], a0, a1, a2, a3, b20, b21);
            MMA_F16(d[5], a0, a1, a2, a3, b22, b23);
            MMA_F16(d[6], a0, a1, a2, a3, b30, b31);
            MMA_F16(d[7], a0, a1, a2, a3, b32, b33);

            a0 = n0; a1 = n1; a2 = n2; a3 = n3;
        }
        #undef WGEN

        float S1sum = dS[0];
        float S2sum = dS[2];

        float dw1 = wcalc(s1r + zs[r << 1],
                          (adjs[((r >> 5) << 9) + r] >> (r & 31)) & 1, M1);
        float dw2 = wcalc(s1r2 + zs[r2 << 1],
                          (adjs[((r2 >> 5) << 9) + r2] >> (r2 & 31)) & 1, M2);

        float inv1 = __fdividef(1.0f, S1sum);
        float inv2 = __fdividef(1.0f, S2sum);
        float wd1 = dw1 * inv1, wd2 = dw2 * inv2;

        float* obase = out + (size_t)b * NN * CF;
        #pragma unroll
        for (int tI = 0; tI < 8; tI++) {
            int nc = tI * 8 + (qid << 1);
            float2 bv = *(const float2*)(bs + nc);
            float df1x = bflo_f(diffA[ph][tI]), df1y = bfhi_f(diffA[ph][tI]);
            float df2x = bflo_f(diffB[ph][tI]), df2y = bfhi_f(diffB[ph][tI]);
            float2 o1, o2;
            o1.x = d[tI][0] * inv1 + wd1 * df1x + bv.x;
            o1.y = d[tI][1] * inv1 + wd1 * df1y + bv.y;
            o2.x = d[tI][2] * inv2 + wd2 * df2x + bv.x;
            o2.y = d[tI][3] * inv2 + wd2 * df2y + bv.y;
            *(float2*)(obase + (size_t)r * CF + nc) = o1;
            *(float2*)(obase + (size_t)r2 * CF + nc) = o2;
        }
    }
}

// ---------------------------------------------------------------------------
extern "C" void kernel_launch(void* const* d_in, const int* in_sizes, int n_in,
                              void* d_out, int out_size) {
    const float* x    = (const float*)d_in[0];
    const int*   adj  = (const int*)d_in[1];
    const float* W    = (const float*)d_in[2];
    const float* a    = (const float*)d_in[3];
    const float* bias = (const float*)d_in[4];
    float* out = (float*)d_out;

    cudaFuncSetAttribute(gat_fused_kernel,
                         cudaFuncAttributeMaxDynamicSharedMemorySize, SMEM_SZ);

    adj_bits_kernel<<<NN, 512>>>(adj);
    gat_fused_kernel<<<BB, 512, SMEM_SZ>>>(x, W, a, bias, out);
}

// round 17
// speedup vs baseline: 1.0928x; 1.0928x over previous
#include <cuda_runtime.h>
#include <cuda_bf16.h>

#define BB 128
#define NN 512
#define CF 64
#define LOG2E 1.4426950408889634f

typedef unsigned int u32;
typedef unsigned long long u64;

// ---------------- scratch ----------------
__device__ u32 g_adjb[NN * 16];

// ---------------- helpers ----------------
__device__ __forceinline__ u32 cvth2(float vh, float vl) {    // f16x2 pack
    u32 r; asm("cvt.rn.f16x2.f32 %0, %1, %2;" : "=r"(r) : "f"(vh), "f"(vl));
    return r;
}
__device__ __forceinline__ float2 h2f2(u32 p) {               // unpack f16x2 -> 2 f32
    float2 r;
    asm("{.reg .f16 lo, hi;\n\t mov.b32 {lo, hi}, %2;\n\t"
        "cvt.f32.f16 %0, lo;\n\t cvt.f32.f16 %1, hi;}"
        : "=f"(r.x), "=f"(r.y) : "r"(p));
    return r;
}
__device__ __forceinline__ u32 ex2h2(u32 x) {                 // packed fp16 2^x
    u32 r; asm("ex2.approx.f16x2 %0, %1;" : "=r"(r) : "r"(x));
    return r;
}
__device__ __forceinline__ u32 smem_u32(const void* p) {
    u32 a;
    asm("{ .reg .u64 t; cvta.to.shared.u64 t, %1; cvt.u32.u64 %0, t; }"
        : "=r"(a) : "l"(p));
    return a;
}
// w = bit ? exp2(lrelu(v) - M) : 0   (v pre-scaled by log2 e; M = row bound)
__device__ __forceinline__ float wcalc(float v, u32 bit, float M) {
    float u = fmaxf(v, 0.2f * v) - M;
    u = bit ? u : -1e38f;
    float e; asm("ex2.approx.f32 %0, %1;" : "=f"(e) : "f"(u));
    return e;
}

#define LDSM4(r0, r1, r2, r3, addr) \
    asm volatile("ldmatrix.sync.aligned.m8n8.x4.shared.b16 {%0,%1,%2,%3}, [%4];" \
        : "=r"(r0), "=r"(r1), "=r"(r2), "=r"(r3) : "r"(addr))

#define LDSM4T(r0, r1, r2, r3, addr) \
    asm volatile("ldmatrix.sync.aligned.m8n8.x4.trans.shared.b16 {%0,%1,%2,%3}, [%4];" \
        : "=r"(r0), "=r"(r1), "=r"(r2), "=r"(r3) : "r"(addr))

#define MMA_F16(d, a0, a1, a2, a3, b0, b1) \
    asm volatile("mma.sync.aligned.m16n8k16.row.col.f32.f16.f16.f32 " \
        "{%0,%1,%2,%3}, {%4,%5,%6,%7}, {%8,%9}, {%0,%1,%2,%3};" \
        : "+f"((d)[0]), "+f"((d)[1]), "+f"((d)[2]), "+f"((d)[3]) \
        : "r"(a0), "r"(a1), "r"(a2), "r"(a3), "r"(b0), "r"(b1))

// swizzled byte offset within 128B-row layout: row j, 4-byte pair index f2 (0..31)
__device__ __forceinline__ u32 swoff(int j, int f2) {
    return (u32)(j * 128 + ((((f2 >> 2) ^ (j & 7))) << 4) + ((f2 & 3) << 2));
}

// ---------------------------------------------------------------------------
// Kernel 1: adj -> bitmask
// ---------------------------------------------------------------------------
__global__ __launch_bounds__(512) void adj_bits_kernel(const int* __restrict__ adj) {
    int row = blockIdx.x;
    int t = threadIdx.x;
    int v = adj[(size_t)row * NN + t];
    u32 m = __ballot_sync(0xffffffffu, v > 0);
    if ((t & 31) == 0) g_adjb[row * 16 + (t >> 5)] = m;
}

// ---------------------------------------------------------------------------
// Kernel 2: fused GEMM + attention. 1 CTA/batch, 512 threads (16 warps).
// Phase 1: hS = x@(W0+W1) fp16 3-pass, h1 = x@W1 fp16 1-pass; diff = hS-2*h1
//          stored to the (dead after phase 1) x_lo smem slice, per-warp-own.
// Phase 2: merged-phase 1-pass fp16 HMMA attention — each B fragment loaded
//          ONCE per chunk and consumed by both 16-row groups (32 rows/warp).
// ---------------------------------------------------------------------------
#define SM_H    0                 // x hi (phase1) / h1 fp16 (phase2): 64KB
#define SM_XLO  65536             // x lo (phase1) / diff fp16 (phase2): 64KB
#define SM_W    131072            // WS_hi, WS_lo, W1 : 3 x 8192
#define SM_ADJ  163840            // chunk-major: [chunk][row] 16x512 u32
#define SM_Z    196608            // 1024 f32: interleaved (p, 0.2p) per j
#define SM_AS   200704            // a vector: 128 f32
#define SM_BIAS 201216            // 64 f32
#define SM_WMAX 201472            // 16 f32
#define SMEM_SZ 201536

__global__ __launch_bounds__(512) void gat_fused_kernel(
    const float* __restrict__ x, const float* __restrict__ W,
    const float* __restrict__ a, const float* __restrict__ bias,
    float* __restrict__ out)
{
    extern __shared__ char smc[];
    int b = blockIdx.x;
    int t = threadIdx.x;
    u32 smb = smem_u32(smc);

    float* zs  = (float*)(smc + SM_Z);
    float* asv = (float*)(smc + SM_AS);
    float* bs  = (float*)(smc + SM_BIAS);
    float* wmx = (float*)(smc + SM_WMAX);
    u32*  adjs = (u32*)(smc + SM_ADJ);

    // ---- stage: x (fp32 -> fp16 hi/lo, swizzled rows), WS/W1, adj, a, bias --
    {
        const float4* xp = (const float4*)(x + (size_t)b * NN * CF);
        #pragma unroll
        for (int k = 0; k < 16; k++) {
            int idx = t + k * 512;
            float4 v = __ldg(xp + idx);
            int row = idx >> 4;
            int f2  = (idx & 15) << 1;
            u32 h0 = cvth2(v.y, v.x);
            float2 f0 = h2f2(h0);
            u32 l0 = cvth2(v.y - f0.y, v.x - f0.x);
            u32 h1 = cvth2(v.w, v.z);
            float2 f1 = h2f2(h1);
            u32 l1 = cvth2(v.w - f1.y, v.z - f1.x);
            u32 o0 = swoff(row, f2), o1 = swoff(row, f2 + 1);
            *(u32*)(smc + SM_H + o0) = h0;
            *(u32*)(smc + SM_XLO + o0) = l0;
            *(u32*)(smc + SM_H + o1) = h1;
            *(u32*)(smc + SM_XLO + o1) = l1;
        }
        const float4* wp = (const float4*)W;
        #pragma unroll
        for (int k = 0; k < 2; k++) {
            int idx = t + k * 512;
            float4 v0 = __ldg(wp + idx);
            float4 v1 = __ldg(wp + 1024 + idx);
            int c = idx >> 4;
            int f2 = (idx & 15) << 1;
            float sx = v0.x + v1.x, sy = v0.y + v1.y;
            float sz = v0.z + v1.z, sw = v0.w + v1.w;
            u32 hs0 = cvth2(sy, sx);
            float2 fs0 = h2f2(hs0);
            u32 ls0 = cvth2(sy - fs0.y, sx - fs0.x);
            u32 hs1 = cvth2(sw, sz);
            float2 fs1 = h2f2(hs1);
            u32 ls1 = cvth2(sw - fs1.y, sz - fs1.x);
            u32 o0 = swoff(c, f2), o1 = swoff(c, f2 + 1);
            *(u32*)(smc + SM_W + o0) = hs0;
            *(u32*)(smc + SM_W + 8192 + o0) = ls0;
            *(u32*)(smc + SM_W + o1) = hs1;
            *(u32*)(smc + SM_W + 8192 + o1) = ls1;
            *(u32*)(smc + SM_W + 16384 + o0) = cvth2(v1.y, v1.x);
            *(u32*)(smc + SM_W + 16384 + o1) = cvth2(v1.w, v1.z);
        }
        #pragma unroll
        for (int k = 0; k < 16; k++)
            adjs[(k << 9) + t] = g_adjb[t * 16 + k];
        if (t < 128) asv[t] = __ldg(&a[t]);
        if (t < 64) bs[t] = __ldg(&bias[t]);
    }
    __syncthreads();

    int lane = t & 31, w = t >> 5;
    int qid = lane & 3, gid = lane >> 2;
    int klane = lane & 15;
    int nhalf = lane >> 4;
    int k7 = klane & 7;
    int cHalf = lane >> 4;

    u32 cswz[4];
    #pragma unroll
    for (int g = 0; g < 4; g++)
        cswz[g] = (u32)(((((g << 1) + nhalf)) ^ k7) << 4);

    // diff slice: warp-own 4KB inside x_lo region (GENERIC pointer arithmetic)
    char* difp = smc + SM_XLO + (w << 12) + (lane << 2);

    // ---------------- phase 1: hS (3-pass) + h1 (1-pass) fp16 HMMA ---------
    float s1reg[2], s1reg2[2];

    #pragma unroll
    for (int rt = 0; rt < 2; rt++) {
        int rbg = w * 32 + rt * 16;
        int rowA = rbg + (lane & 15);
        u32 aBase = smb + SM_H + rowA * 128;
        int r7x = rowA & 7;

        float d0[8][4], d1[8][4];
        #pragma unroll
        for (int i = 0; i < 8; i++)
            #pragma unroll
            for (int e = 0; e < 4; e++) { d0[i][e] = 0.f; d1[i][e] = 0.f; }

        #pragma unroll
        for (int ks = 0; ks < 4; ks++) {
            u32 achunk = (u32)(((2 * ks + cHalf) ^ r7x) << 4);
            u32 ah0, ah1, ah2, ah3, al0, al1, al2, al3;
            LDSM4(ah0, ah1, ah2, ah3, aBase + achunk);
            LDSM4(al0, al1, al2, al3, aBase + 65536 + achunk);
            u32 kb = (u32)((ks * 16 + klane) * 128);
            #pragma unroll
            for (int g = 0; g < 4; g++) {
                u32 cs = cswz[g];
                u32 b0, b1, b2, b3;
                LDSM4T(b0, b1, b2, b3, smb + SM_W + cs + kb);           // WS hi
                MMA_F16(d0[2 * g],     ah0, ah1, ah2, ah3, b0, b1);
                MMA_F16(d0[2 * g + 1], ah0, ah1, ah2, ah3, b2, b3);
                MMA_F16(d0[2 * g],     al0, al1, al2, al3, b0, b1);
                MMA_F16(d0[2 * g + 1], al0, al1, al2, al3, b2, b3);
                LDSM4T(b0, b1, b2, b3, smb + SM_W + 8192 + cs + kb);    // WS lo
                MMA_F16(d0[2 * g],     ah0, ah1, ah2, ah3, b0, b1);
                MMA_F16(d0[2 * g + 1], ah0, ah1, ah2, ah3, b2, b3);
                LDSM4T(b0, b1, b2, b3, smb + SM_W + 16384 + cs + kb);   // W1
                MMA_F16(d1[2 * g],     ah0, ah1, ah2, ah3, b0, b1);
                MMA_F16(d1[2 * g + 1], ah0, ah1, ah2, ah3, b2, b3);
            }
        }

        // epilogue: s1/s2 from hS, diff = hS - 2*h1 -> x_lo slice (own rows,
        // whose x_lo inputs this warp has already consumed), h1 fp16 -> smem
        int r = rbg + gid, r2 = r + 8;
        char* dslice = difp + (rt << 11);
        float s1pA = 0.f, s2pA = 0.f, s1pB = 0.f, s2pB = 0.f;
        #pragma unroll
        for (int tI = 0; tI < 8; tI++) {
            int nc = tI * 8 + (qid << 1);
            float2 a1v = *(const float2*)(asv + nc);
            float2 a2v = *(const float2*)(asv + 64 + nc);
            int f2 = nc >> 1;
            {
                float hSa = d0[tI][0], hSb = d0[tI][1];
                float h1a = d1[tI][0], h1b = d1[tI][1];
                s1pA += hSa * a1v.x + hSb * a1v.y;
                s2pA += hSa * a2v.x + hSb * a2v.y;
                *(u32*)(dslice + ((tI << 1) << 7)) =
                    cvth2(hSb - 2.f * h1b, hSa - 2.f * h1a);
                *(u32*)(smc + SM_H + swoff(r, f2)) = cvth2(h1b, h1a);
            }
            {
                float hSa = d0[tI][2], hSb = d0[tI][3];
                float h1a = d1[tI][2], h1b = d1[tI][3];
                s1pB += hSa * a1v.x + hSb * a1v.y;
                s2pB += hSa * a2v.x + hSb * a2v.y;
                *(u32*)(dslice + (((tI << 1) + 1) << 7)) =
                    cvth2(hSb - 2.f * h1b, hSa - 2.f * h1a);
                *(u32*)(smc + SM_H + swoff(r2, f2)) = cvth2(h1b, h1a);
            }
        }
        s1pA += __shfl_xor_sync(0xffffffffu, s1pA, 1);
        s1pA += __shfl_xor_sync(0xffffffffu, s1pA, 2);
        s2pA += __shfl_xor_sync(0xffffffffu, s2pA, 1);
        s2pA += __shfl_xor_sync(0xffffffffu, s2pA, 2);
        s1pB += __shfl_xor_sync(0xffffffffu, s1pB, 1);
        s1pB += __shfl_xor_sync(0xffffffffu, s1pB, 2);
        s2pB += __shfl_xor_sync(0xffffffffu, s2pB, 1);
        s2pB += __shfl_xor_sync(0xffffffffu, s2pB, 2);
        s1reg[rt]  = s1pA * LOG2E;
        s1reg2[rt] = s1pB * LOG2E;
        if (qid == 0) {
            float p1 = s2pA * LOG2E, p2 = s2pB * LOG2E;
            zs[(r << 1)]      = p1;
            zs[(r << 1) + 1]  = 0.2f * p1;
            zs[(r2 << 1)]     = p2;
            zs[(r2 << 1) + 1] = 0.2f * p2;
        }
    }
    __syncthreads();   // h1 fp16 B-tiles + z table + diff visible

    // ---- global max of s2 (for fp16-safe weight scaling) ----
    {
        float m = zs[(t & 511) << 1];
        #pragma unroll
        for (int o = 16; o; o >>= 1)
            m = fmaxf(m, __shfl_xor_sync(0xffffffffu, m, o));
        if (lane == 0) wmx[w] = m;
    }
    __syncthreads();
    float maxS2 = wmx[0];
    #pragma unroll
    for (int k = 1; k < 16; k++) maxS2 = fmaxf(maxS2, wmx[k]);

    // ---------------- phase 2: merged-phase 1-pass fp16 HMMA ---------------
    u32 hbc[4];
    #pragma unroll
    for (int g = 0; g < 4; g++)
        hbc[g] = smb + SM_H + cswz[g];

    const u32 ONES = 0x3C003C00u;   // fp16 (1.0, 1.0)
    int rb0 = w * 32 + gid;          // ph0 rows rb0, rb0+8; ph1: +16, +24

    float M1v[2], M2v[2], A1c[2], B1c[2], A2c[2], B2c[2];
    #pragma unroll
    for (int ph = 0; ph < 2; ph++) {
        float s1r = s1reg[ph], s1r2 = s1reg2[ph];
        float vm1 = s1r + maxS2, vm2 = s1r2 + maxS2;
        float M1 = fmaxf(vm1, 0.2f * vm1);
        float M2 = fmaxf(vm2, 0.2f * vm2);
        M1v[ph] = M1; M2v[ph] = M2;
        A1c[ph] = s1r - M1;  B1c[ph] = 0.2f * s1r - M1;
        A2c[ph] = s1r2 - M2; B2c[ph] = 0.2f * s1r2 - M2;
    }

    float d[2][8][4];
    #pragma unroll
    for (int p = 0; p < 2; p++)
        #pragma unroll
        for (int i = 0; i < 8; i++)
            #pragma unroll
            for (int k = 0; k < 4; k++) d[p][i][k] = 0.f;
    float dS[2][4] = {{0.f, 0.f, 0.f, 0.f}, {0.f, 0.f, 0.f, 0.f}};

    #pragma unroll 1
    for (int c = 0; c < 32; c++) {
        // B fragments for this chunk: loaded ONCE, used by both row groups
        u32 kb = (u32)(((c << 4) + klane) << 7);
        u32 b00, b01, b02, b03, b10, b11, b12, b13;
        u32 b20, b21, b22, b23, b30, b31, b32, b33;
        LDSM4T(b00, b01, b02, b03, hbc[0] + kb);
        LDSM4T(b10, b11, b12, b13, hbc[1] + kb);
        LDSM4T(b20, b21, b22, b23, hbc[2] + kb);
        LDSM4T(b30, b31, b32, b33, hbc[3] + kb);

        int j0 = c << 4;
        float4 z0 = *(const float4*)(zs + ((j0 + (qid << 1)) << 1));
        float4 z1 = *(const float4*)(zs + ((j0 + 8 + (qid << 1)) << 1));
        int sh = ((c & 1) << 4) + (qid << 1);
        const u32* adjc = adjs + ((c >> 1) << 9);

        #pragma unroll
        for (int ph = 0; ph < 2; ph++) {
            int rr = rb0 + ph * 16, rr2 = rr + 8;
            u32 br  = adjc[rr] >> sh;
            u32 br2 = adjc[rr2] >> sh;
            float A1 = A1c[ph], B1 = B1c[ph];
            float A2 = A2c[ph], B2 = B2c[ph];

            float u00 = fmaxf(A1 + z0.x, B1 + z0.y);
            float u01 = fmaxf(A1 + z0.z, B1 + z0.w);
            float u08 = fmaxf(A1 + z1.x, B1 + z1.y);
            float u09 = fmaxf(A1 + z1.z, B1 + z1.w);
            float u10 = fmaxf(A2 + z0.x, B2 + z0.y);
            float u11 = fmaxf(A2 + z0.z, B2 + z0.w);
            float u18 = fmaxf(A2 + z1.x, B2 + z1.y);
            float u19 = fmaxf(A2 + z1.z, B2 + z1.w);

            u00 = (br & 1u)    ? u00 : -1e4f;
            u01 = (br & 2u)    ? u01 : -1e4f;
            u08 = (br & 256u)  ? u08 : -1e4f;
            u09 = (br & 512u)  ? u09 : -1e4f;
            u10 = (br2 & 1u)   ? u10 : -1e4f;
            u11 = (br2 & 2u)   ? u11 : -1e4f;
            u18 = (br2 & 256u) ? u18 : -1e4f;
            u19 = (br2 & 512u) ? u19 : -1e4f;

            u32 a0 = ex2h2(cvth2(u01, u00));
            u32 a1 = ex2h2(cvth2(u11, u10));
            u32 a2 = ex2h2(cvth2(u09, u08));
            u32 a3 = ex2h2(cvth2(u19, u18));

            MMA_F16(dS[ph], a0, a1, a2, a3, ONES, ONES);   // row sums

            MMA_F16(d[ph][0], a0, a1, a2, a3, b00, b01);
            MMA_F16(d[ph][1], a0, a1, a2, a3, b02, b03);
            MMA_F16(d[ph][2], a0, a1, a2, a3, b10, b11);
            MMA_F16(d[ph][3], a0, a1, a2, a3, b12, b13);
            MMA_F16(d[ph][4], a0, a1, a2, a3, b20, b21);
            MMA_F16(d[ph][5], a0, a1, a2, a3, b22, b23);
            MMA_F16(d[ph][6], a0, a1, a2, a3, b30, b31);
            MMA_F16(d[ph][7], a0, a1, a2, a3, b32, b33);
        }
    }

    // ---- epilogue: normalize + diag correction (diff from smem) + bias ----
    float* obase = out + (size_t)b * NN * CF;
    #pragma unroll
    for (int ph = 0; ph < 2; ph++) {
        int rr = rb0 + ph * 16, rr2 = rr + 8;
        float S1sum = dS[ph][0];
        float S2sum = dS[ph][2];

        float dw1 = wcalc(s1reg[ph] + zs[rr << 1],
                          (adjs[((rr >> 5) << 9) + rr] >> (rr & 31)) & 1, M1v[ph]);
        float dw2 = wcalc(s1reg2[ph] + zs[rr2 << 1],
                          (adjs[((rr2 >> 5) << 9) + rr2] >> (rr2 & 31)) & 1, M2v[ph]);

        float inv1 = __fdividef(1.0f, S1sum);
        float inv2 = __fdividef(1.0f, S2sum);
        float wd1 = dw1 * inv1, wd2 = dw2 * inv2;

        char* dslice = difp + (ph << 11);
        #pragma unroll
        for (int tI = 0; tI < 8; tI++) {
            int nc = tI * 8 + (qid << 1);
            float2 bv = *(const float2*)(bs + nc);
            u32 dA = *(const u32*)(dslice + ((tI << 1) << 7));
            u32 dB = *(const u32*)(dslice + (((tI << 1) + 1) << 7));
            float2 df1 = h2f2(dA);
            float2 df2 = h2f2(dB);
            float2 o1, o2;
            o1.x = d[ph][tI][0] * inv1 + wd1 * df1.x + bv.x;
            o1.y = d[ph][tI][1] * inv1 + wd1 * df1.y + bv.y;
            o2.x = d[ph][tI][2] * inv2 + wd2 * df2.x + bv.x;
            o2.y = d[ph][tI][3] * inv2 + wd2 * df2.y + bv.y;
            *(float2*)(obase + (size_t)rr * CF + nc) = o1;
            *(float2*)(obase + (size_t)rr2 * CF + nc) = o2;
        }
    }
}

// ---------------------------------------------------------------------------
extern "C" void kernel_launch(void* const* d_in, const int* in_sizes, int n_in,
                              void* d_out, int out_size) {
    const float* x    = (const float*)d_in[0];
    const int*   adj  = (const int*)d_in[1];
    const float* W    = (const float*)d_in[2];
    const float* a    = (const float*)d_in[3];
    const float* bias = (const float*)d_in[4];
    float* out = (float*)d_out;

    cudaFuncSetAttribute(gat_fused_kernel,
                         cudaFuncAttributeMaxDynamicSharedMemorySize, SMEM_SZ);

    adj_bits_kernel<<<NN, 512>>>(adj);
    gat_fused_kernel<<<BB, 512, SMEM_SZ>>>(x, W, a, bias, out);
}